// round 6
// baseline (speedup 1.0000x reference)
#include <cuda_runtime.h>
#include <math.h>
#include <stdint.h>

#define BB 4
#define TT 2048
#define CC 1024
#define NH 16
#define HD 64
#define BT (BB*TT)      // 8192
#define C3 (3*CC)       // 3072

// Scratch (device globals; no allocation allowed)
__device__ float g_qkv[BT * C3];   // [BT, 3C]
__device__ float g_q[BT * CC];     // [B,H,T,64]  tf32-rounded, pre-scaled 1/8
__device__ float g_k[BT * CC];     // [B,H,64,T]  (d-major!) tf32-rounded
__device__ float g_v[BT * CC];     // [B,H,T,64]  tf32-rounded
__device__ float g_attn[BT * CC];  // [B,T,C]

// ---------------------------------------------------------------------------
// helpers
// ---------------------------------------------------------------------------
__device__ __forceinline__ unsigned f2tf(float x) {
    unsigned r;
    asm("cvt.rna.tf32.f32 %0, %1;" : "=r"(r) : "f"(x));
    return r;
}

__device__ __forceinline__ void mma8(float* c, const unsigned* a,
                                     unsigned b0, unsigned b1) {
    asm("mma.sync.aligned.m16n8k8.row.col.f32.tf32.tf32.f32 "
        "{%0,%1,%2,%3}, {%4,%5,%6,%7}, {%8,%9}, {%0,%1,%2,%3};"
        : "+f"(c[0]), "+f"(c[1]), "+f"(c[2]), "+f"(c[3])
        : "r"(a[0]), "r"(a[1]), "r"(a[2]), "r"(a[3]), "r"(b0), "r"(b1));
}

__device__ __forceinline__ uint32_t sptr(const void* p) {
    return (uint32_t)__cvta_generic_to_shared(p);
}
__device__ __forceinline__ void cp16(uint32_t dst, const void* src) {
    asm volatile("cp.async.cg.shared.global [%0], [%1], 16;" :: "r"(dst), "l"(src));
}
__device__ __forceinline__ void cp_commit() {
    asm volatile("cp.async.commit_group;");
}
__device__ __forceinline__ void cp_wait0() {
    asm volatile("cp.async.wait_group 0;");
}
__device__ __forceinline__ void cp_wait1() {
    asm volatile("cp.async.wait_group 1;");
}

// ---------------------------------------------------------------------------
// tf32 tensor-core GEMM (unchanged): 128x128x16 tiles, 8 warps.
// ---------------------------------------------------------------------------
__global__ __launch_bounds__(256) void gemm_tf32(
    const float* __restrict__ A, const float* __restrict__ Bm,
    float* __restrict__ Cm, int M, int N, int K)
{
    __shared__ unsigned As[16 * 136];
    __shared__ unsigned Bs[16 * 136];

    int tid = threadIdx.x;
    int lane = tid & 31;
    int warp = tid >> 5;
    int gid = lane >> 2, tig = lane & 3;
    int warp_m = warp >> 2, warp_n = warp & 3;
    int bm = blockIdx.y, bn = blockIdx.x;

    const float* Abase = A + (size_t)(bm * 128) * K;
    const float* Bbase = Bm + (size_t)bn * 128;

    float acc[4][4][4];
    #pragma unroll
    for (int mt = 0; mt < 4; mt++)
        #pragma unroll
        for (int nt = 0; nt < 4; nt++)
            #pragma unroll
            for (int e = 0; e < 4; e++) acc[mt][nt][e] = 0.f;

    int am = tid >> 2;
    int af4 = tid & 3;
    int bk = tid >> 5;
    int bn4 = (tid & 31) * 4;

    for (int k0 = 0; k0 < K; k0 += 16) {
        float4 a0v = *(const float4*)(Abase + (size_t)am * K + k0 + af4 * 4);
        float4 a1v = *(const float4*)(Abase + (size_t)(am + 64) * K + k0 + af4 * 4);
        float4 b0v = *(const float4*)(Bbase + (size_t)(k0 + bk) * N + bn4);
        float4 b1v = *(const float4*)(Bbase + (size_t)(k0 + bk + 8) * N + bn4);
        __syncthreads();
        {
            int swz = 8 * af4;
            int kb4 = af4 * 4;
            As[(kb4 + 0) * 136 + (am ^ swz)] = f2tf(a0v.x);
            As[(kb4 + 1) * 136 + (am ^ swz)] = f2tf(a0v.y);
            As[(kb4 + 2) * 136 + (am ^ swz)] = f2tf(a0v.z);
            As[(kb4 + 3) * 136 + (am ^ swz)] = f2tf(a0v.w);
            int am2 = am + 64;
            As[(kb4 + 0) * 136 + (am2 ^ swz)] = f2tf(a1v.x);
            As[(kb4 + 1) * 136 + (am2 ^ swz)] = f2tf(a1v.y);
            As[(kb4 + 2) * 136 + (am2 ^ swz)] = f2tf(a1v.z);
            As[(kb4 + 3) * 136 + (am2 ^ swz)] = f2tf(a1v.w);

            uint4 t0 = make_uint4(f2tf(b0v.x), f2tf(b0v.y), f2tf(b0v.z), f2tf(b0v.w));
            uint4 t1 = make_uint4(f2tf(b1v.x), f2tf(b1v.y), f2tf(b1v.z), f2tf(b1v.w));
            *(uint4*)&Bs[bk * 136 + bn4] = t0;
            *(uint4*)&Bs[(bk + 8) * 136 + bn4] = t1;
        }
        __syncthreads();

        #pragma unroll
        for (int ks = 0; ks < 16; ks += 8) {
            unsigned afr[4][4];
            unsigned bfr[4][2];
            int swz1 = 8 * ((ks >> 2) & 3);
            int swz2 = 8 * (((ks + 4) >> 2) & 3);
            #pragma unroll
            for (int mt = 0; mt < 4; mt++) {
                int m = warp_m * 64 + mt * 16 + gid;
                afr[mt][0] = As[(ks + tig) * 136 + (m ^ swz1)];
                afr[mt][1] = As[(ks + tig) * 136 + ((m + 8) ^ swz1)];
                afr[mt][2] = As[(ks + tig + 4) * 136 + (m ^ swz2)];
                afr[mt][3] = As[(ks + tig + 4) * 136 + ((m + 8) ^ swz2)];
            }
            #pragma unroll
            for (int nt = 0; nt < 4; nt++) {
                int n = warp_n * 32 + nt * 8 + gid;
                bfr[nt][0] = Bs[(ks + tig) * 136 + n];
                bfr[nt][1] = Bs[(ks + tig + 4) * 136 + n];
            }
            #pragma unroll
            for (int mt = 0; mt < 4; mt++)
                #pragma unroll
                for (int nt = 0; nt < 4; nt++)
                    mma8(acc[mt][nt], afr[mt], bfr[nt][0], bfr[nt][1]);
        }
    }

    #pragma unroll
    for (int mt = 0; mt < 4; mt++)
        #pragma unroll
        for (int nt = 0; nt < 4; nt++) {
            int row = bm * 128 + warp_m * 64 + mt * 16 + gid;
            int col = bn * 128 + warp_n * 32 + nt * 8 + tig * 2;
            *(float2*)&Cm[(size_t)row * N + col] =
                make_float2(acc[mt][nt][0], acc[mt][nt][1]);
            *(float2*)&Cm[(size_t)(row + 8) * N + col] =
                make_float2(acc[mt][nt][2], acc[mt][nt][3]);
        }
}

// ---------------------------------------------------------------------------
// Split qkv -> q,v in [B,H,T,64] and K in [B,H,64,T] (d-major, so the attn
// kernel can cp.async K^T tiles directly). RoPE + tf32 rounding at write.
// ---------------------------------------------------------------------------
__global__ void rope_split_kernel()
{
    int idx = blockIdx.x * blockDim.x + threadIdx.x;
    const int total = BB * NH * TT * 32;
    if (idx >= total) return;

    int jj = idx & 31;
    int tmp = idx >> 5;
    int t = tmp & (TT - 1);
    tmp >>= 11;
    int h = tmp & (NH - 1);
    int b = tmp >> 4;
    int bh = b * NH + h;

    const float LOG1E4 = 9.210340371976184f;
    float inv_freq = expf(-(float)jj * (LOG1E4 / 32.0f));
    float ang = (float)t * inv_freq;
    float cs = cosf(ang), sn = sinf(ang);

    size_t src_row = (size_t)(b * TT + t) * C3;
    int col = h * HD + jj;

    float q1 = g_qkv[src_row + col];
    float q2 = g_qkv[src_row + col + 32];
    float k1 = g_qkv[src_row + CC + col];
    float k2 = g_qkv[src_row + CC + col + 32];
    float v1 = g_qkv[src_row + 2 * CC + col];
    float v2 = g_qkv[src_row + 2 * CC + col + 32];

    size_t dst = ((size_t)bh * TT + t) * HD + jj;
    g_q[dst]      = __uint_as_float(f2tf((q1 * cs - q2 * sn) * 0.125f));
    g_q[dst + 32] = __uint_as_float(f2tf((q2 * cs + q1 * sn) * 0.125f));
    g_v[dst]      = __uint_as_float(f2tf(v1));
    g_v[dst + 32] = __uint_as_float(f2tf(v2));

    // K transposed: [bh][d][t]
    size_t kdst = ((size_t)bh * HD + jj) * TT + t;
    g_k[kdst]            = __uint_as_float(f2tf(k1 * cs - k2 * sn));
    g_k[kdst + 32 * TT]  = __uint_as_float(f2tf(k2 * cs + k1 * sn));
}

// ---------------------------------------------------------------------------
// Flash attention (causal), tf32 mma, v3:
//  - 32 queries per warp (2 m16 strips) -> smem B-fragment traffic per query
//    halved vs v2.
//  - K^T and V tiles in smem, stride 72 words, 16B-chunk XOR swizzle
//    (chunk c4 stored at c4 ^ ((row>>2)&7)<<2). Reads use the R4-verified
//    conflict-free pattern  buf[(ks+tig)*72 + (n ^ ((ks>>2)&7)<<2)].
//  - double-buffered cp.async; heavy CTAs (large qb) scheduled first.
// CTA = 256 queries, 8 warps; warp w owns rows [32w, 32w+32).
// ---------------------------------------------------------------------------
#define KV_STR 72
#define KV_WORDS (64 * KV_STR)
#define ATTN_SMEM_WORDS (4 * KV_WORDS)

__global__ __launch_bounds__(256, 1) void attn_mma_kernel()
{
    extern __shared__ float sm[];
    float* sK[2] = { sm, sm + KV_WORDS };
    float* sV[2] = { sm + 2 * KV_WORDS, sm + 3 * KV_WORDS };

    int tid = threadIdx.x;
    int lane = tid & 31;
    int warp = tid >> 5;
    int gid = lane >> 2, tig = lane & 3;
    int qb = gridDim.x - 1 - blockIdx.x;   // heavy blocks first
    int bh = blockIdx.y;

    const float* Qg = g_q + ((size_t)bh * TT + qb * 256) * HD;
    const float* Kg = g_k + (size_t)bh * HD * TT;    // [d][t]
    const float* Vg = g_v + (size_t)bh * TT * HD;    // [t][d]

    int mbase = warp * 32;
    int r1 = qb * 256 + mbase + gid;       // 4 owned rows: r1, +8, +16, +24

    int kb_max = 4 * qb + 3;

    // issue tile 0 into buffer 0 (K rows = d, V rows = kv)
    #pragma unroll
    for (int it = 0; it < 4; it++) {
        int cid = tid + 256 * it;
        int r = cid >> 4;
        int c4 = (cid & 15) * 4;
        int swz = ((r >> 2) & 7) << 2;
        cp16(sptr(sK[0] + r * KV_STR + (c4 ^ swz)), Kg + (size_t)r * TT + c4);
        cp16(sptr(sV[0] + r * KV_STR + (c4 ^ swz)), Vg + (size_t)r * 64 + c4);
    }
    cp_commit();

    // Q fragments (2 m16 tiles), loaded once
    unsigned qa[8][8];
    #pragma unroll
    for (int c = 0; c < 8; c++) {
        int d0 = c * 8 + tig;
        qa[c][0] = __float_as_uint(Qg[(size_t)(mbase + gid) * 64 + d0]);
        qa[c][1] = __float_as_uint(Qg[(size_t)(mbase + gid + 8) * 64 + d0]);
        qa[c][2] = __float_as_uint(Qg[(size_t)(mbase + gid) * 64 + d0 + 4]);
        qa[c][3] = __float_as_uint(Qg[(size_t)(mbase + gid + 8) * 64 + d0 + 4]);
        qa[c][4] = __float_as_uint(Qg[(size_t)(mbase + gid + 16) * 64 + d0]);
        qa[c][5] = __float_as_uint(Qg[(size_t)(mbase + gid + 24) * 64 + d0]);
        qa[c][6] = __float_as_uint(Qg[(size_t)(mbase + gid + 16) * 64 + d0 + 4]);
        qa[c][7] = __float_as_uint(Qg[(size_t)(mbase + gid + 24) * 64 + d0 + 4]);
    }

    float oacc[8][8];
    #pragma unroll
    for (int nt = 0; nt < 8; nt++)
        #pragma unroll
        for (int e = 0; e < 8; e++) oacc[nt][e] = 0.f;
    float rm[4] = {-1e30f, -1e30f, -1e30f, -1e30f};
    float rl[4] = {0.f, 0.f, 0.f, 0.f};

    for (int kb = 0; kb <= kb_max; kb++) {
        int cur = kb & 1;
        if (kb < kb_max) {
            int nb = cur ^ 1;
            const float* Kn = Kg + (size_t)(kb + 1) * 64;          // t offset
            const float* Vn = Vg + (size_t)(kb + 1) * 64 * 64;
            #pragma unroll
            for (int it = 0; it < 4; it++) {
                int cid = tid + 256 * it;
                int r = cid >> 4;
                int c4 = (cid & 15) * 4;
                int swz = ((r >> 2) & 7) << 2;
                cp16(sptr(sK[nb] + r * KV_STR + (c4 ^ swz)), Kn + (size_t)r * TT + c4);
                cp16(sptr(sV[nb] + r * KV_STR + (c4 ^ swz)), Vn + (size_t)r * 64 + c4);
            }
            cp_commit();
            cp_wait1();
        } else {
            cp_wait0();
        }
        __syncthreads();

        const float* K_ = sK[cur];
        const float* V_ = sV[cur];

        // S = Q K^T : 32 x 64 per warp
        float sacc[8][8];
        #pragma unroll
        for (int nt = 0; nt < 8; nt++)
            #pragma unroll
            for (int e = 0; e < 8; e++) sacc[nt][e] = 0.f;

        #pragma unroll
        for (int c = 0; c < 8; c++) {
            int ks = c * 8;
            int c1 = ((ks >> 2) & 7) << 2;
            int c2 = (((ks + 4) >> 2) & 7) << 2;
            #pragma unroll
            for (int nt = 0; nt < 8; nt++) {
                int n = nt * 8 + gid;
                unsigned b0 = __float_as_uint(K_[(ks + tig) * KV_STR + (n ^ c1)]);
                unsigned b1 = __float_as_uint(K_[(ks + tig + 4) * KV_STR + (n ^ c2)]);
                mma8(sacc[nt] + 0, qa[c] + 0, b0, b1);
                mma8(sacc[nt] + 4, qa[c] + 4, b0, b1);
            }
        }

        // causal mask (diagonal region spans 4 kb tiles)
        if (kb >= 4 * qb) {
            #pragma unroll
            for (int nt = 0; nt < 8; nt++) {
                int colb = kb * 64 + nt * 8 + tig * 2;
                #pragma unroll
                for (int s = 0; s < 4; s++) {
                    int rg = r1 + s * 8;
                    if (colb + 0 > rg) sacc[nt][2 * s + 0] = -1e30f;
                    if (colb + 1 > rg) sacc[nt][2 * s + 1] = -1e30f;
                }
            }
        }

        // online softmax per owned row (quad reductions)
        float corr[4];
        #pragma unroll
        for (int s = 0; s < 4; s++) {
            float mx = -1e30f;
            #pragma unroll
            for (int nt = 0; nt < 8; nt++)
                mx = fmaxf(mx, fmaxf(sacc[nt][2 * s], sacc[nt][2 * s + 1]));
            mx = fmaxf(mx, __shfl_xor_sync(0xffffffffu, mx, 1));
            mx = fmaxf(mx, __shfl_xor_sync(0xffffffffu, mx, 2));
            float mn = fmaxf(rm[s], mx);
            corr[s] = __expf(rm[s] - mn);
            rm[s] = mn;
            float sum = 0.f;
            #pragma unroll
            for (int nt = 0; nt < 8; nt++) {
                float p0 = __expf(sacc[nt][2 * s] - mn);
                float p1 = __expf(sacc[nt][2 * s + 1] - mn);
                sacc[nt][2 * s] = p0;
                sacc[nt][2 * s + 1] = p1;
                sum += p0 + p1;
            }
            sum += __shfl_xor_sync(0xffffffffu, sum, 1);
            sum += __shfl_xor_sync(0xffffffffu, sum, 2);
            rl[s] = rl[s] * corr[s] + sum;
        }
        #pragma unroll
        for (int nt = 0; nt < 8; nt++)
            #pragma unroll
            for (int s = 0; s < 4; s++) {
                oacc[nt][2 * s] *= corr[s];
                oacc[nt][2 * s + 1] *= corr[s];
            }

        // O += P @ V, P transposed C->A layout via intra-quad shuffles
        int base = lane & 28;
        int src0 = base + (tig >> 1);
        int src2 = src0 + 2;
        int odd = tig & 1;
        #pragma unroll
        for (int c = 0; c < 8; c++) {
            unsigned pa[8];
            #pragma unroll
            for (int t2 = 0; t2 < 2; t2++) {   // tile0 / tile1
                int o4 = t2 * 4;
                float e0 = __shfl_sync(0xffffffffu, sacc[c][o4 + 0], src0);
                float e1 = __shfl_sync(0xffffffffu, sacc[c][o4 + 1], src0);
                float g0 = __shfl_sync(0xffffffffu, sacc[c][o4 + 0], src2);
                float g1 = __shfl_sync(0xffffffffu, sacc[c][o4 + 1], src2);
                float f0 = __shfl_sync(0xffffffffu, sacc[c][o4 + 2], src0);
                float f1 = __shfl_sync(0xffffffffu, sacc[c][o4 + 3], src0);
                float h0 = __shfl_sync(0xffffffffu, sacc[c][o4 + 2], src2);
                float h1 = __shfl_sync(0xffffffffu, sacc[c][o4 + 3], src2);
                pa[o4 + 0] = f2tf(odd ? e1 : e0);
                pa[o4 + 1] = f2tf(odd ? f1 : f0);
                pa[o4 + 2] = f2tf(odd ? g1 : g0);
                pa[o4 + 3] = f2tf(odd ? h1 : h0);
            }
            int ks = c * 8;
            int c1 = ((ks >> 2) & 7) << 2;
            int c2 = (((ks + 4) >> 2) & 7) << 2;
            #pragma unroll
            for (int dt = 0; dt < 8; dt++) {
                int n = dt * 8 + gid;
                unsigned b0 = __float_as_uint(V_[(ks + tig) * KV_STR + (n ^ c1)]);
                unsigned b1 = __float_as_uint(V_[(ks + tig + 4) * KV_STR + (n ^ c2)]);
                mma8(oacc[dt] + 0, pa + 0, b0, b1);
                mma8(oacc[dt] + 4, pa + 4, b0, b1);
            }
        }
        __syncthreads();
    }

    // epilogue: normalize, write [B,T,C]
    int b = bh >> 4;
    int h = bh & (NH - 1);
    #pragma unroll
    for (int s = 0; s < 4; s++) {
        float il = 1.f / rl[s];
        int t = qb * 256 + mbase + s * 8 + gid;
        float* dst = g_attn + ((size_t)(b * TT + t)) * CC + h * 64;
        #pragma unroll
        for (int nt = 0; nt < 8; nt++) {
            int d = nt * 8 + tig * 2;
            *(float2*)&dst[d] = make_float2(oacc[nt][2 * s] * il,
                                            oacc[nt][2 * s + 1] * il);
        }
    }
}

// ---------------------------------------------------------------------------
extern "C" void kernel_launch(void* const* d_in, const int* in_sizes, int n_in,
                              void* d_out, int out_size)
{
    const float* x     = (const float*)d_in[0];
    const float* w_qkv = (const float*)d_in[1];
    const float* w_out = (const float*)d_in[2];
    float* out = (float*)d_out;

    float *qkv_p, *attn_p;
    cudaGetSymbolAddress((void**)&qkv_p,  g_qkv);
    cudaGetSymbolAddress((void**)&attn_p, g_attn);

    // 1) QKV projection
    {
        dim3 grid(C3 / 128, BT / 128);
        gemm_tf32<<<grid, 256>>>(x, w_qkv, qkv_p, BT, C3, CC);
    }

    // 2) split + RoPE (+ tf32 rounding; K stored d-major)
    {
        int total = BB * NH * TT * 32;
        rope_split_kernel<<<(total + 255) / 256, 256>>>();
    }

    // 3) flash attention (tensor cores, 32q/warp, cp.async double-buffered)
    {
        int smem_bytes = ATTN_SMEM_WORDS * sizeof(float);
        cudaFuncSetAttribute(attn_mma_kernel,
                             cudaFuncAttributeMaxDynamicSharedMemorySize,
                             smem_bytes);
        dim3 grid(TT / 256, BB * NH);
        attn_mma_kernel<<<grid, 256, smem_bytes>>>();
    }

    // 4) output projection
    {
        dim3 grid(CC / 128, BT / 128);
        gemm_tf32<<<grid, 256>>>(attn_p, w_out, out, BT, CC, CC);
    }
}